// round 13
// baseline (speedup 1.0000x reference)
#include <cuda_runtime.h>
#include <cuda_fp16.h>
#include <cstdint>

#define N_NODES 100000
#define N_EDGES 1600000
#define HID 128
#define IN_DIM 8
#define SCH 512
#define SNB ((N_NODES + SCH - 1) / SCH)  // 196

// ---------------- scratch (static __device__, no allocation) ----------------
__device__ __half g_h1h[(size_t)N_NODES * HID];
__device__ __half g_h2h[(size_t)N_NODES * HID];
__device__ __half g_wt2h[128 * 256];
__device__ __half g_wt2l[128 * 256];
__device__ __half g_wt3h[128 * 256];
__device__ __half g_wt3l[128 * 256];
__device__ int g_cnt_c[N_NODES];
__device__ int g_cnt_d[N_NODES];
__device__ int g_rp_c[N_NODES + 1];
__device__ int g_rp_d[N_NODES + 1];
__device__ int g_cur_c[N_NODES];
__device__ int g_cur_d[N_NODES];
__device__ int g_src_c[N_EDGES];
__device__ int g_src_d[N_EDGES];
__device__ int g_bsum_c[SNB];
__device__ int g_bsum_d[SNB];
__device__ int g_boff_c[SNB];
__device__ int g_boff_d[SNB];

// ---------------- CSR build (per-list) ----------------
__global__ void zero1(int* a, int n) {
    int i = blockIdx.x * blockDim.x + threadIdx.x;
    int st = gridDim.x * blockDim.x;
    for (; i < n; i += st) a[i] = 0;
}

__global__ void hist1(const int* __restrict__ ei, int E, int* cnt) {
    int i = blockIdx.x * blockDim.x + threadIdx.x;
    int st = gridDim.x * blockDim.x;
    int E4 = E >> 2;
    const int4* d4 = (const int4*)(ei + E);
    for (int j = i; j < E4; j += st) {
        int4 v = d4[j];
        atomicAdd(&cnt[v.x], 1);
        atomicAdd(&cnt[v.y], 1);
        atomicAdd(&cnt[v.z], 1);
        atomicAdd(&cnt[v.w], 1);
    }
    for (int j = E4 * 4 + i; j < E; j += st) atomicAdd(&cnt[ei[E + j]], 1);
}

__global__ __launch_bounds__(256) void scan_p1(const int* __restrict__ cnt,
                                               int* __restrict__ bsum, int n) {
    __shared__ int s[8];
    int b = blockIdx.x, t = threadIdx.x;
    int i0 = b * SCH + t;
    int v = 0;
    if (i0 < n) v += cnt[i0];
    if (i0 + 256 < n) v += cnt[i0 + 256];
#pragma unroll
    for (int o = 16; o >= 1; o >>= 1) v += __shfl_xor_sync(0xffffffffu, v, o);
    if ((t & 31) == 0) s[t >> 5] = v;
    __syncthreads();
    if (t < 8) {
        int w = s[t];
#pragma unroll
        for (int o = 4; o >= 1; o >>= 1) w += __shfl_xor_sync(0xffu, w, o);
        if (t == 0) bsum[b] = w;
    }
}

__global__ __launch_bounds__(256) void scan_p2(const int* __restrict__ bsum,
                                               int* __restrict__ boff,
                                               int* __restrict__ rp, int nb, int n) {
    __shared__ int s[256];
    int t = threadIdx.x;
    int v = (t < nb) ? bsum[t] : 0;
    s[t] = v;
    __syncthreads();
#pragma unroll
    for (int o = 1; o < 256; o <<= 1) {
        int u = (t >= o) ? s[t - o] : 0;
        __syncthreads();
        s[t] += u;
        __syncthreads();
    }
    if (t < nb) boff[t] = s[t] - v;
    if (t == 255) rp[n] = s[255];
}

__global__ __launch_bounds__(256) void scan_p3(const int* __restrict__ cnt,
                                               const int* __restrict__ boff,
                                               int* __restrict__ rp,
                                               int* __restrict__ cur, int n) {
    __shared__ int wsum[8];
    int b = blockIdx.x, t = threadIdx.x;
    int lane = t & 31, wrp = t >> 5;
    int i0 = b * SCH + 2 * t;
    int c0 = (i0 < n) ? cnt[i0] : 0;
    int c1 = (i0 + 1 < n) ? cnt[i0 + 1] : 0;
    int ps = c0 + c1;
    int x = ps;
#pragma unroll
    for (int o = 1; o < 32; o <<= 1) {
        int u = __shfl_up_sync(0xffffffffu, x, o);
        if (lane >= o) x += u;
    }
    if (lane == 31) wsum[wrp] = x;
    __syncthreads();
    if (t < 8) {
        int w = wsum[t];
        int y = w;
#pragma unroll
        for (int o = 1; o < 8; o <<= 1) {
            int u = __shfl_up_sync(0xffu, y, o);
            if (t >= o) y += u;
        }
        wsum[t] = y - w;
    }
    __syncthreads();
    int woff = wsum[wrp];
    int pre = boff[b] + woff + (x - ps);
    if (i0 < n) { rp[i0] = pre; cur[i0] = pre; }
    if (i0 + 1 < n) { rp[i0 + 1] = pre + c0; cur[i0 + 1] = pre + c0; }
}

__global__ void fill1(const int* __restrict__ ei, int E, int* cur,
                      int* __restrict__ srcl) {
    int i = blockIdx.x * blockDim.x + threadIdx.x;
    int st = gridDim.x * blockDim.x;
    int E4 = E >> 2;
    const int4* s4 = (const int4*)ei;
    const int4* d4 = (const int4*)(ei + E);
    for (int j = i; j < E4; j += st) {
        int4 s = s4[j];
        int4 d = d4[j];
        srcl[atomicAdd(&cur[d.x], 1)] = s.x;
        srcl[atomicAdd(&cur[d.y], 1)] = s.y;
        srcl[atomicAdd(&cur[d.z], 1)] = s.z;
        srcl[atomicAdd(&cur[d.w], 1)] = s.w;
    }
    for (int j = E4 * 4 + i; j < E; j += st)
        srcl[atomicAdd(&cur[ei[E + j]], 1)] = ei[j];
}

// ---------------- weight prep: W[k][n] fp32 -> Wt[n][256] fp16 hi/lo ----------------
__global__ void wprep(const float* __restrict__ wl2, const float* __restrict__ wr2,
                      const float* __restrict__ wl3, const float* __restrict__ wr3,
                      __half* w2h, __half* w2l, __half* w3h, __half* w3l) {
    int i = blockIdx.x * blockDim.x + threadIdx.x;
    if (i >= 2 * 128 * 256) return;
    int layer = i >> 15;
    int rem = i & 32767;
    int nrow = rem >> 8, k = rem & 255;
    const float* wlm = layer ? wl3 : wl2;
    const float* wrm = layer ? wr3 : wr2;
    float v = (k < 128) ? wlm[k * 128 + nrow] : wrm[(k - 128) * 128 + nrow];
    __half h = __float2half(v);
    __half l = __float2half(v - __half2float(h));
    (layer ? w3h : w2h)[nrow * 256 + k] = h;
    (layer ? w3l : w2l)[nrow * 256 + k] = l;
}

// ---------------- layer 1 fused: gather-mean(d=8) + GEMM + norm + tanh ----------------
__global__ void layer1_fused(const float* __restrict__ x,
                             const int* __restrict__ rp, const int* __restrict__ src,
                             const float* __restrict__ wl, const float* __restrict__ wr,
                             const float* __restrict__ bias,
                             __half* __restrict__ outh, int n) {
    __shared__ float s_wl[IN_DIM * HID];
    __shared__ float s_wr[IN_DIM * HID];
    __shared__ float s_b[HID];
    for (int i = threadIdx.x; i < IN_DIM * HID; i += blockDim.x) {
        s_wl[i] = wl[i];
        s_wr[i] = wr[i];
    }
    if (threadIdx.x < HID) s_b[threadIdx.x] = bias[threadIdx.x];
    __syncthreads();

    int warp = threadIdx.x >> 5, lane = threadIdx.x & 31;
    int node = blockIdx.x * (blockDim.x >> 5) + warp;
    if (node >= n) return;
    int grp = lane >> 3, dim = lane & 7;

    int b = __ldg(rp + node), e = __ldg(rp + node + 1);
    float acc8 = 0.f;
    for (int j = b + grp; j < e; j += 4) {
        int s0 = __ldg(src + j);
        acc8 += __ldg(x + (size_t)s0 * IN_DIM + dim);
    }
    acc8 += __shfl_xor_sync(0xffffffffu, acc8, 8);
    acc8 += __shfl_xor_sync(0xffffffffu, acc8, 16);
    acc8 *= 1.f / fmaxf((float)(e - b), 1.f);

    float my_x = __ldg(x + (size_t)node * IN_DIM + dim);

    float xs[8], as[8];
#pragma unroll
    for (int k = 0; k < 8; k++) {
        xs[k] = __shfl_sync(0xffffffffu, my_x, k);
        as[k] = __shfl_sync(0xffffffffu, acc8, k);
    }
    float acc[4];
#pragma unroll
    for (int c = 0; c < 4; c++) {
        int j = lane + 32 * c;
        float a = s_b[j];
#pragma unroll
        for (int k = 0; k < 8; k++)
            a += as[k] * s_wl[k * HID + j] + xs[k] * s_wr[k * HID + j];
        acc[c] = a;
    }
    float ss = acc[0] * acc[0] + acc[1] * acc[1] + acc[2] * acc[2] + acc[3] * acc[3];
#pragma unroll
    for (int o = 16; o >= 1; o >>= 1) ss += __shfl_xor_sync(0xffffffffu, ss, o);
    float invn = 1.f / fmaxf(sqrtf(ss), 1e-12f);
#pragma unroll
    for (int c = 0; c < 4; c++) {
        float v = tanhf(acc[c] * invn);
        outh[(size_t)node * HID + lane + 32 * c] = __float2half(v);
    }
}

// ---------------- fused gather-mean + fp16 TC GEMM + norm + tanh, layers 2/3 ----------------
#define BM 128
#define LDH 40     // B smem row stride (halves)
#define LDA 136    // A smem row stride (halves): 272B = 17 granules -> conflict-free

__device__ __forceinline__ uint32_t smem_u32(const void* p) {
    return (uint32_t)__cvta_generic_to_shared(p);
}
__device__ __forceinline__ void ldsm_x4(uint32_t* r, uint32_t addr) {
    asm volatile("ldmatrix.sync.aligned.m8n8.x4.shared.b16 {%0,%1,%2,%3}, [%4];"
                 : "=r"(r[0]), "=r"(r[1]), "=r"(r[2]), "=r"(r[3]) : "r"(addr));
}
__device__ __forceinline__ void mma_f16(float* c, const uint32_t* a,
                                        uint32_t b0, uint32_t b1) {
    asm volatile(
        "mma.sync.aligned.m16n8k16.row.col.f32.f16.f16.f32 "
        "{%0,%1,%2,%3}, {%4,%5,%6,%7}, {%8,%9}, {%0,%1,%2,%3};"
        : "+f"(c[0]), "+f"(c[1]), "+f"(c[2]), "+f"(c[3])
        : "r"(a[0]), "r"(a[1]), "r"(a[2]), "r"(a[3]), "r"(b0), "r"(b1));
}

// dynamic smem: Am[128][LDA] | Ah[128][LDA] | Bhs[128][LDH] | Bls[128][LDH] | ss[2][128]
#define SM_AM 0
#define SM_AH (128 * LDA)
#define SM_BH (2 * 128 * LDA)
#define SM_BL (2 * 128 * LDA + 128 * LDH)
#define SM_SS (2 * 128 * LDA + 2 * 128 * LDH)
#define SMEM_FUSED ((SM_SS) * 2 + 2 * BM * 4)   // bytes

extern __shared__ __half sdyn[];

__global__ __launch_bounds__(256, 2) void layer23_fused(
    const __half* __restrict__ hinh,
    const int* __restrict__ rp, const int* __restrict__ src,
    const __half* __restrict__ wth, const __half* __restrict__ wtl,
    const float* __restrict__ bias, float* __restrict__ out,
    __half* __restrict__ outh, int n) {
    __half* Am = sdyn + SM_AM;
    __half* Ah = sdyn + SM_AH;
    __half* Bhs = sdyn + SM_BH;
    __half* Bls = sdyn + SM_BL;
    float* ss_part = (float*)(sdyn + SM_SS);

    int t = threadIdx.x;
    int row0 = blockIdx.x * BM;
    int wid = t >> 5, lane = t & 31;
    int warp_m = wid & 3;
    int warp_n = wid >> 2;
    int g = lane >> 2, tig = lane & 3;
    int m_st = t >> 1, part = t & 1;
    int ic_st = (row0 + m_st) < n ? (row0 + m_st) : n - 1;

    // ---- prefetch B chunk 0 into regs ----
    uint4 rbh0, rbh1, rbl0, rbl1;
    {
        const uint4* bh = (const uint4*)(wth + m_st * 256 + part * 16);
        const uint4* bl = (const uint4*)(wtl + m_st * 256 + part * 16);
        rbh0 = bh[0]; rbh1 = bh[1];
        rbl0 = bl[0]; rbl1 = bl[1];
    }

    // ---- stage hin rows (self term, chunks 4-7) ----
    {
        const uint4* hsrc = (const uint4*)(hinh + (size_t)ic_st * HID + part * 64);
        uint4* hd = (uint4*)(Ah + m_st * LDA + part * 64);
#pragma unroll
        for (int q = 0; q < 8; q++) hd[q] = hsrc[q];
    }

    // ---- phase A: gather-mean for this CTA's 128 nodes into Am ----
    {
        int half = lane >> 4, li = lane & 15;
        for (int i = 0; i < 16; i++) {
            int m = wid * 16 + i;
            int node = row0 + m;
            int ic = node < n ? node : n - 1;
            int b = __ldg(rp + ic), e = __ldg(rp + ic + 1);
            float acc[8];
#pragma unroll
            for (int k = 0; k < 8; k++) acc[k] = 0.f;
            int j = b + half;
            for (; j + 2 < e; j += 4) {
                int s0 = __ldg(src + j);
                int s1 = __ldg(src + j + 2);
                uint4 r0 = *(const uint4*)(hinh + (size_t)s0 * HID + li * 8);
                uint4 r1 = *(const uint4*)(hinh + (size_t)s1 * HID + li * 8);
#pragma unroll
                for (int q = 0; q < 4; q++) {
                    float2 f0 = __half22float2(*(const __half2*)(&r0.x + q));
                    float2 f1 = __half22float2(*(const __half2*)(&r1.x + q));
                    acc[2 * q]     += f0.x + f1.x;
                    acc[2 * q + 1] += f0.y + f1.y;
                }
            }
            if (j < e) {
                int s0 = __ldg(src + j);
                uint4 r0 = *(const uint4*)(hinh + (size_t)s0 * HID + li * 8);
#pragma unroll
                for (int q = 0; q < 4; q++) {
                    float2 f0 = __half22float2(*(const __half2*)(&r0.x + q));
                    acc[2 * q]     += f0.x;
                    acc[2 * q + 1] += f0.y;
                }
            }
#pragma unroll
            for (int k = 0; k < 8; k++)
                acc[k] += __shfl_xor_sync(0xffffffffu, acc[k], 16);
            if (half == 0) {
                float inv = 1.f / fmaxf((float)(e - b), 1.f);
                uint4 o;
                ((__half2*)&o)[0] = __floats2half2_rn(acc[0] * inv, acc[1] * inv);
                ((__half2*)&o)[1] = __floats2half2_rn(acc[2] * inv, acc[3] * inv);
                ((__half2*)&o)[2] = __floats2half2_rn(acc[4] * inv, acc[5] * inv);
                ((__half2*)&o)[3] = __floats2half2_rn(acc[6] * inv, acc[7] * inv);
                *(uint4*)(Am + m * LDA + li * 8) = o;
            }
        }
    }
    __syncthreads();

    // ---- phase B: MMA over 8 K-chunks ----
    uint32_t bh_base = smem_u32(Bhs) +
        ((warp_n * 64 + (lane & 15)) * LDH + (lane >> 4) * 8) * 2;
    uint32_t bl_base = smem_u32(Bls) +
        ((warp_n * 64 + (lane & 15)) * LDH + (lane >> 4) * 8) * 2;
    const uint32_t R16B = 16 * LDH * 2;
    const uint32_t R16A = 16 * LDA * 2;
    uint32_t am_base = smem_u32(Am) +
        ((warp_m * 32 + (lane & 15)) * LDA + (lane >> 4) * 8) * 2;
    uint32_t ah_base = smem_u32(Ah) +
        ((warp_m * 32 + (lane & 15)) * LDA + (lane >> 4) * 8) * 2;

    float acc[2][8][4];
#pragma unroll
    for (int i = 0; i < 2; i++)
#pragma unroll
        for (int j = 0; j < 8; j++)
#pragma unroll
            for (int c = 0; c < 4; c++) acc[i][j][c] = 0.f;

    for (int c = 0; c < 8; c++) {
        __half* bhd = Bhs + m_st * LDH + part * 16;
        *(uint4*)bhd = rbh0;
        *(uint4*)(bhd + 8) = rbh1;
        __half* bld = Bls + m_st * LDH + part * 16;
        *(uint4*)bld = rbl0;
        *(uint4*)(bld + 8) = rbl1;
        __syncthreads();

        if (c < 7) {
            const uint4* bh = (const uint4*)(wth + m_st * 256 + (c + 1) * 32 + part * 16);
            const uint4* bl = (const uint4*)(wtl + m_st * 256 + (c + 1) * 32 + part * 16);
            rbh0 = bh[0]; rbh1 = bh[1];
            rbl0 = bl[0]; rbl1 = bl[1];
        }

        uint32_t abase = ((c < 4) ? am_base : ah_base) + (c & 3) * 64;  // 32 halves=64B
#pragma unroll
        for (int s = 0; s < 2; s++) {
            uint32_t a[2][4];
            ldsm_x4(a[0], abase + s * 32);
            ldsm_x4(a[1], abase + s * 32 + R16A);
#pragma unroll
            for (int p = 0; p < 4; p++) {
                uint32_t bh[4], bl[4];
                ldsm_x4(bh, bh_base + p * R16B + s * 32);
                ldsm_x4(bl, bl_base + p * R16B + s * 32);
#pragma unroll
                for (int mi = 0; mi < 2; mi++) {
                    mma_f16(acc[mi][2 * p],     a[mi], bh[0], bh[2]);
                    mma_f16(acc[mi][2 * p],     a[mi], bl[0], bl[2]);
                    mma_f16(acc[mi][2 * p + 1], a[mi], bh[1], bh[3]);
                    mma_f16(acc[mi][2 * p + 1], a[mi], bl[1], bl[3]);
                }
            }
        }
        __syncthreads();
    }

    // ---- epilogue: +bias, row L2 norm, tanh ----
    float2 bv[8];
#pragma unroll
    for (int nt = 0; nt < 8; nt++)
        bv[nt] = *(const float2*)(bias + warp_n * 64 + nt * 8 + 2 * tig);

#pragma unroll
    for (int mi = 0; mi < 2; mi++) {
#pragma unroll
        for (int h = 0; h < 2; h++) {
            float ss = 0.f;
#pragma unroll
            for (int nt = 0; nt < 8; nt++) {
                acc[mi][nt][2 * h]     += bv[nt].x;
                acc[mi][nt][2 * h + 1] += bv[nt].y;
                ss += acc[mi][nt][2 * h] * acc[mi][nt][2 * h]
                    + acc[mi][nt][2 * h + 1] * acc[mi][nt][2 * h + 1];
            }
            ss += __shfl_xor_sync(0xffffffffu, ss, 1);
            ss += __shfl_xor_sync(0xffffffffu, ss, 2);
            if (tig == 0)
                ss_part[warp_n * BM + warp_m * 32 + mi * 16 + h * 8 + g] = ss;
        }
    }
    __syncthreads();

#pragma unroll
    for (int mi = 0; mi < 2; mi++) {
#pragma unroll
        for (int h = 0; h < 2; h++) {
            int rloc = warp_m * 32 + mi * 16 + h * 8 + g;
            int gi = row0 + rloc;
            if (gi >= n) continue;
            float tot = ss_part[rloc] + ss_part[BM + rloc];
            float invn = 1.f / fmaxf(sqrtf(tot), 1e-12f);
#pragma unroll
            for (int nt = 0; nt < 8; nt++) {
                float2 o;
                o.x = tanhf(acc[mi][nt][2 * h] * invn);
                o.y = tanhf(acc[mi][nt][2 * h + 1] * invn);
                size_t off = (size_t)gi * HID + warp_n * 64 + nt * 8 + 2 * tig;
                if (out) *(float2*)(out + off) = o;
                if (outh) *(__half2*)(outh + off) = __floats2half2_rn(o.x, o.y);
            }
        }
    }
}

// ---------------- launch ----------------
extern "C" void kernel_launch(void* const* d_in, const int* in_sizes, int n_in,
                              void* d_out, int out_size) {
    const float* x       = (const float*)d_in[0];
    const int*   ei_conn = (const int*)d_in[1];
    const int*   ei_dest = (const int*)d_in[2];
    const float* w_l1 = (const float*)d_in[3];
    const float* w_r1 = (const float*)d_in[4];
    const float* b1   = (const float*)d_in[5];
    const float* w_l2 = (const float*)d_in[6];
    const float* w_r2 = (const float*)d_in[7];
    const float* b2   = (const float*)d_in[8];
    const float* w_l3 = (const float*)d_in[9];
    const float* w_r3 = (const float*)d_in[10];
    const float* b3   = (const float*)d_in[11];
    float* out = (float*)d_out;

    const int n = N_NODES;
    const int E = in_sizes[1] / 2;

    __half *p_h1h, *p_h2h, *p_w2h, *p_w2l, *p_w3h, *p_w3l;
    int *p_cnt_c, *p_cnt_d, *p_rp_c, *p_rp_d, *p_cur_c, *p_cur_d, *p_src_c, *p_src_d;
    int *p_bs_c, *p_bs_d, *p_bo_c, *p_bo_d;
    cudaGetSymbolAddress((void**)&p_h1h, g_h1h);
    cudaGetSymbolAddress((void**)&p_h2h, g_h2h);
    cudaGetSymbolAddress((void**)&p_w2h, g_wt2h);
    cudaGetSymbolAddress((void**)&p_w2l, g_wt2l);
    cudaGetSymbolAddress((void**)&p_w3h, g_wt3h);
    cudaGetSymbolAddress((void**)&p_w3l, g_wt3l);
    cudaGetSymbolAddress((void**)&p_cnt_c, g_cnt_c);
    cudaGetSymbolAddress((void**)&p_cnt_d, g_cnt_d);
    cudaGetSymbolAddress((void**)&p_rp_c, g_rp_c);
    cudaGetSymbolAddress((void**)&p_rp_d, g_rp_d);
    cudaGetSymbolAddress((void**)&p_cur_c, g_cur_c);
    cudaGetSymbolAddress((void**)&p_cur_d, g_cur_d);
    cudaGetSymbolAddress((void**)&p_src_c, g_src_c);
    cudaGetSymbolAddress((void**)&p_src_d, g_src_d);
    cudaGetSymbolAddress((void**)&p_bs_c, g_bsum_c);
    cudaGetSymbolAddress((void**)&p_bs_d, g_bsum_d);
    cudaGetSymbolAddress((void**)&p_bo_c, g_boff_c);
    cudaGetSymbolAddress((void**)&p_bo_d, g_boff_d);

    static cudaStream_t sB = nullptr;
    static cudaEvent_t evFork = nullptr, evJoin = nullptr;
    static bool attr_set = false;
    if (!sB) {
        cudaStreamCreateWithFlags(&sB, cudaStreamNonBlocking);
        cudaEventCreateWithFlags(&evFork, cudaEventDisableTiming);
        cudaEventCreateWithFlags(&evJoin, cudaEventDisableTiming);
    }
    if (!attr_set) {
        cudaFuncSetAttribute(layer23_fused, cudaFuncAttributeMaxDynamicSharedMemorySize,
                             SMEM_FUSED);
        attr_set = true;
    }

    // ---- fork: weight prep + dest-list CSR on side stream ----
    cudaEventRecord(evFork, 0);
    cudaStreamWaitEvent(sB, evFork, 0);
    wprep<<<(2 * 128 * 256 + 255) / 256, 256, 0, sB>>>(w_l2, w_r2, w_l3, w_r3,
                                                       p_w2h, p_w2l, p_w3h, p_w3l);
    zero1<<<(n + 255) / 256, 256, 0, sB>>>(p_cnt_d, n);
    hist1<<<512, 256, 0, sB>>>(ei_dest, E, p_cnt_d);
    scan_p1<<<SNB, 256, 0, sB>>>(p_cnt_d, p_bs_d, n);
    scan_p2<<<1, 256, 0, sB>>>(p_bs_d, p_bo_d, p_rp_d, SNB, n);
    scan_p3<<<SNB, 256, 0, sB>>>(p_cnt_d, p_bo_d, p_rp_d, p_cur_d, n);
    fill1<<<512, 256, 0, sB>>>(ei_dest, E, p_cur_d, p_src_d);
    cudaEventRecord(evJoin, sB);

    // ---- main stream: conn-list CSR + layer 1 ----
    zero1<<<(n + 255) / 256, 256>>>(p_cnt_c, n);
    hist1<<<512, 256>>>(ei_conn, E, p_cnt_c);
    scan_p1<<<SNB, 256>>>(p_cnt_c, p_bs_c, n);
    scan_p2<<<1, 256>>>(p_bs_c, p_bo_c, p_rp_c, SNB, n);
    scan_p3<<<SNB, 256>>>(p_cnt_c, p_bo_c, p_rp_c, p_cur_c, n);
    fill1<<<512, 256>>>(ei_conn, E, p_cur_c, p_src_c);
    layer1_fused<<<(n + 7) / 8, 256>>>(x, p_rp_c, p_src_c, w_l1, w_r1, b1, p_h1h, n);

    // ---- join, then layer 2 (dest) fused gather+GEMM ----
    cudaStreamWaitEvent(0, evJoin, 0);
    layer23_fused<<<(n + BM - 1) / BM, 256, SMEM_FUSED>>>(
        p_h1h, p_rp_d, p_src_d, p_w2h, p_w2l, b2, nullptr, p_h2h, n);

    // ---- layer 3 (conn) fused gather+GEMM ----
    layer23_fused<<<(n + BM - 1) / BM, 256, SMEM_FUSED>>>(
        p_h2h, p_rp_c, p_src_c, p_w3h, p_w3l, b3, out, nullptr, n);
}

// round 14
// speedup vs baseline: 1.2391x; 1.2391x over previous
#include <cuda_runtime.h>
#include <cuda_fp16.h>
#include <cstdint>

#define N_NODES 100000
#define N_EDGES 1600000
#define HID 128
#define IN_DIM 8
#define SCH 512
#define SNB ((N_NODES + SCH - 1) / SCH)  // 196

// ---------------- scratch (static __device__, no allocation) ----------------
__device__ __half g_h1h[(size_t)N_NODES * HID];
__device__ __half g_h2h[(size_t)N_NODES * HID];
__device__ __half g_aggh[(size_t)N_NODES * HID];
__device__ float g_agg8[(size_t)N_NODES * IN_DIM];
__device__ int g_cnt8[N_NODES];
__device__ __half g_wt2h[128 * 256];
__device__ __half g_wt2l[128 * 256];
__device__ __half g_wt3h[128 * 256];
__device__ __half g_wt3l[128 * 256];
__device__ int g_cnt_c[N_NODES];
__device__ int g_cnt_d[N_NODES];
__device__ int g_rp_c[N_NODES + 1];
__device__ int g_rp_d[N_NODES + 1];
__device__ int g_cur_c[N_NODES];
__device__ int g_cur_d[N_NODES];
__device__ int g_src_c[N_EDGES];
__device__ int g_src_d[N_EDGES];
__device__ int g_bsum_c[SNB];
__device__ int g_bsum_d[SNB];
__device__ int g_boff_c[SNB];
__device__ int g_boff_d[SNB];

// ---------------- helpers ----------------
__device__ __forceinline__ void red4(float* p, float4 v) {
    asm volatile("red.global.add.v4.f32 [%0], {%1,%2,%3,%4};"
                 :: "l"(p), "f"(v.x), "f"(v.y), "f"(v.z), "f"(v.w) : "memory");
}

// ---------------- CSR build (per-list) ----------------
__global__ void zero1(int* a, int n) {
    int i = blockIdx.x * blockDim.x + threadIdx.x;
    int st = gridDim.x * blockDim.x;
    for (; i < n; i += st) a[i] = 0;
}

__global__ void zero_l1(float* a, size_t na, int* b, int nb) {
    size_t i = (size_t)blockIdx.x * blockDim.x + threadIdx.x;
    size_t st = (size_t)gridDim.x * blockDim.x;
    for (size_t j = i; j < na; j += st) a[j] = 0.f;
    for (size_t j = i; j < (size_t)nb; j += st) b[j] = 0;
}

__global__ void hist1(const int* __restrict__ ei, int E, int* cnt) {
    int i = blockIdx.x * blockDim.x + threadIdx.x;
    int st = gridDim.x * blockDim.x;
    int E4 = E >> 2;
    const int4* d4 = (const int4*)(ei + E);
    for (int j = i; j < E4; j += st) {
        int4 v = d4[j];
        atomicAdd(&cnt[v.x], 1);
        atomicAdd(&cnt[v.y], 1);
        atomicAdd(&cnt[v.z], 1);
        atomicAdd(&cnt[v.w], 1);
    }
    for (int j = E4 * 4 + i; j < E; j += st) atomicAdd(&cnt[ei[E + j]], 1);
}

__global__ __launch_bounds__(256) void scan_p1(const int* __restrict__ cnt,
                                               int* __restrict__ bsum, int n) {
    __shared__ int s[8];
    int b = blockIdx.x, t = threadIdx.x;
    int i0 = b * SCH + t;
    int v = 0;
    if (i0 < n) v += cnt[i0];
    if (i0 + 256 < n) v += cnt[i0 + 256];
#pragma unroll
    for (int o = 16; o >= 1; o >>= 1) v += __shfl_xor_sync(0xffffffffu, v, o);
    if ((t & 31) == 0) s[t >> 5] = v;
    __syncthreads();
    if (t < 8) {
        int w = s[t];
#pragma unroll
        for (int o = 4; o >= 1; o >>= 1) w += __shfl_xor_sync(0xffu, w, o);
        if (t == 0) bsum[b] = w;
    }
}

__global__ __launch_bounds__(256) void scan_p2(const int* __restrict__ bsum,
                                               int* __restrict__ boff,
                                               int* __restrict__ rp, int nb, int n) {
    __shared__ int s[256];
    int t = threadIdx.x;
    int v = (t < nb) ? bsum[t] : 0;
    s[t] = v;
    __syncthreads();
#pragma unroll
    for (int o = 1; o < 256; o <<= 1) {
        int u = (t >= o) ? s[t - o] : 0;
        __syncthreads();
        s[t] += u;
        __syncthreads();
    }
    if (t < nb) boff[t] = s[t] - v;
    if (t == 255) rp[n] = s[255];
}

__global__ __launch_bounds__(256) void scan_p3(const int* __restrict__ cnt,
                                               const int* __restrict__ boff,
                                               int* __restrict__ rp,
                                               int* __restrict__ cur, int n) {
    __shared__ int wsum[8];
    int b = blockIdx.x, t = threadIdx.x;
    int lane = t & 31, wrp = t >> 5;
    int i0 = b * SCH + 2 * t;
    int c0 = (i0 < n) ? cnt[i0] : 0;
    int c1 = (i0 + 1 < n) ? cnt[i0 + 1] : 0;
    int ps = c0 + c1;
    int x = ps;
#pragma unroll
    for (int o = 1; o < 32; o <<= 1) {
        int u = __shfl_up_sync(0xffffffffu, x, o);
        if (lane >= o) x += u;
    }
    if (lane == 31) wsum[wrp] = x;
    __syncthreads();
    if (t < 8) {
        int w = wsum[t];
        int y = w;
#pragma unroll
        for (int o = 1; o < 8; o <<= 1) {
            int u = __shfl_up_sync(0xffu, y, o);
            if (t >= o) y += u;
        }
        wsum[t] = y - w;
    }
    __syncthreads();
    int woff = wsum[wrp];
    int pre = boff[b] + woff + (x - ps);
    if (i0 < n) { rp[i0] = pre; cur[i0] = pre; }
    if (i0 + 1 < n) { rp[i0 + 1] = pre + c0; cur[i0 + 1] = pre + c0; }
}

__global__ void fill1(const int* __restrict__ ei, int E, int* cur,
                      int* __restrict__ srcl) {
    int i = blockIdx.x * blockDim.x + threadIdx.x;
    int st = gridDim.x * blockDim.x;
    int E4 = E >> 2;
    const int4* s4 = (const int4*)ei;
    const int4* d4 = (const int4*)(ei + E);
    for (int j = i; j < E4; j += st) {
        int4 s = s4[j];
        int4 d = d4[j];
        srcl[atomicAdd(&cur[d.x], 1)] = s.x;
        srcl[atomicAdd(&cur[d.y], 1)] = s.y;
        srcl[atomicAdd(&cur[d.z], 1)] = s.z;
        srcl[atomicAdd(&cur[d.w], 1)] = s.w;
    }
    for (int j = E4 * 4 + i; j < E; j += st)
        srcl[atomicAdd(&cur[ei[E + j]], 1)] = ei[j];
}

// ---------------- weight prep: W[k][n] fp32 -> Wt[n][256] fp16 hi/lo ----------------
__global__ void wprep(const float* __restrict__ wl2, const float* __restrict__ wr2,
                      const float* __restrict__ wl3, const float* __restrict__ wr3,
                      __half* w2h, __half* w2l, __half* w3h, __half* w3l) {
    int i = blockIdx.x * blockDim.x + threadIdx.x;
    if (i >= 2 * 128 * 256) return;
    int layer = i >> 15;
    int rem = i & 32767;
    int nrow = rem >> 8, k = rem & 255;
    const float* wlm = layer ? wl3 : wl2;
    const float* wrm = layer ? wr3 : wr2;
    float v = (k < 128) ? wlm[k * 128 + nrow] : wrm[(k - 128) * 128 + nrow];
    __half h = __float2half(v);
    __half l = __float2half(v - __half2float(h));
    (layer ? w3h : w2h)[nrow * 256 + k] = h;
    (layer ? w3l : w2l)[nrow * 256 + k] = l;
}

// ---------------- layer-1 scatter aggregation (d=8, no CSR) ----------------
__global__ void scatter8(const float* __restrict__ x, const int* __restrict__ ei,
                         int E, float* __restrict__ agg8, int* __restrict__ cnt8) {
    int e = blockIdx.x * blockDim.x + threadIdx.x;
    if (e >= E) return;
    int s = __ldg(ei + e);
    int d = __ldg(ei + E + e);
    const float4* xr = (const float4*)(x + (size_t)s * IN_DIM);
    float4 a = xr[0], b = xr[1];
    float* dp = agg8 + (size_t)d * IN_DIM;
    red4(dp, a);
    red4(dp + 4, b);
    asm volatile("red.global.add.s32 [%0], %1;" :: "l"(cnt8 + d), "r"(1) : "memory");
}

// ---------------- layer 1: d_in=8 -> 128, one warp per node ----------------
__global__ void layer1_direct(const float* __restrict__ x, const float* __restrict__ agg8,
                              const int* __restrict__ cnt8,
                              const float* __restrict__ wl, const float* __restrict__ wr,
                              const float* __restrict__ bias,
                              __half* __restrict__ outh, int n) {
    __shared__ float s_wl[IN_DIM * HID];
    __shared__ float s_wr[IN_DIM * HID];
    __shared__ float s_b[HID];
    for (int i = threadIdx.x; i < IN_DIM * HID; i += blockDim.x) {
        s_wl[i] = wl[i];
        s_wr[i] = wr[i];
    }
    if (threadIdx.x < HID) s_b[threadIdx.x] = bias[threadIdx.x];
    __syncthreads();

    int warp = threadIdx.x >> 5, lane = threadIdx.x & 31;
    int node = blockIdx.x * (blockDim.x >> 5) + warp;
    if (node >= n) return;

    // lanes 0-7: x row; lanes 8-15: agg8 row; lane 16: count
    float my = 0.f;
    if (lane < 8)       my = __ldg(x + (size_t)node * IN_DIM + lane);
    else if (lane < 16) my = __ldg(agg8 + (size_t)node * IN_DIM + (lane - 8));
    else if (lane == 16) my = (float)__ldg(cnt8 + node);
    float iv = 1.f / fmaxf(__shfl_sync(0xffffffffu, my, 16), 1.f);
    float xs[8], as[8];
#pragma unroll
    for (int k = 0; k < 8; k++) {
        xs[k] = __shfl_sync(0xffffffffu, my, k);
        as[k] = __shfl_sync(0xffffffffu, my, 8 + k) * iv;
    }
    float acc[4];
#pragma unroll
    for (int c = 0; c < 4; c++) {
        int j = lane + 32 * c;
        float a = s_b[j];
#pragma unroll
        for (int k = 0; k < 8; k++)
            a += as[k] * s_wl[k * HID + j] + xs[k] * s_wr[k * HID + j];
        acc[c] = a;
    }
    float ss = acc[0] * acc[0] + acc[1] * acc[1] + acc[2] * acc[2] + acc[3] * acc[3];
#pragma unroll
    for (int o = 16; o >= 1; o >>= 1) ss += __shfl_xor_sync(0xffffffffu, ss, o);
    float invn = 1.f / fmaxf(sqrtf(ss), 1e-12f);
#pragma unroll
    for (int c = 0; c < 4; c++) {
        float v = tanhf(acc[c] * invn);
        outh[(size_t)node * HID + lane + 32 * c] = __float2half(v);
    }
}

// ---------------- gather-mean over fp16 rows -> fp16 mean, d=128 ----------------
__global__ void gather128h(const __half* __restrict__ h, const int* __restrict__ rp,
                           const int* __restrict__ src, __half* __restrict__ outh, int n) {
    int node = (blockIdx.x * blockDim.x + threadIdx.x) >> 5;
    int lane = threadIdx.x & 31;
    if (node >= n) return;
    int half = lane >> 4, li = lane & 15;
    int b = __ldg(rp + node), e = __ldg(rp + node + 1);
    float acc[8];
#pragma unroll
    for (int k = 0; k < 8; k++) acc[k] = 0.f;

    int j = b + half;
    for (; j + 2 < e; j += 4) {
        int s0 = __ldg(src + j);
        int s1 = __ldg(src + j + 2);
        uint4 r0 = *(const uint4*)(h + (size_t)s0 * HID + li * 8);
        uint4 r1 = *(const uint4*)(h + (size_t)s1 * HID + li * 8);
#pragma unroll
        for (int q = 0; q < 4; q++) {
            float2 f0 = __half22float2(*(const __half2*)(&r0.x + q));
            float2 f1 = __half22float2(*(const __half2*)(&r1.x + q));
            acc[2 * q]     += f0.x + f1.x;
            acc[2 * q + 1] += f0.y + f1.y;
        }
    }
    if (j < e) {
        int s0 = __ldg(src + j);
        uint4 r0 = *(const uint4*)(h + (size_t)s0 * HID + li * 8);
#pragma unroll
        for (int q = 0; q < 4; q++) {
            float2 f0 = __half22float2(*(const __half2*)(&r0.x + q));
            acc[2 * q]     += f0.x;
            acc[2 * q + 1] += f0.y;
        }
    }
#pragma unroll
    for (int k = 0; k < 8; k++)
        acc[k] += __shfl_xor_sync(0xffffffffu, acc[k], 16);

    if (half == 0) {
        float inv = 1.f / fmaxf((float)(e - b), 1.f);
        uint4 o;
        ((__half2*)&o)[0] = __floats2half2_rn(acc[0] * inv, acc[1] * inv);
        ((__half2*)&o)[1] = __floats2half2_rn(acc[2] * inv, acc[3] * inv);
        ((__half2*)&o)[2] = __floats2half2_rn(acc[4] * inv, acc[5] * inv);
        ((__half2*)&o)[3] = __floats2half2_rn(acc[6] * inv, acc[7] * inv);
        *(uint4*)(outh + (size_t)node * HID + li * 8) = o;
    }
}

// ---------------- fp16 tensor-core GEMM with ldmatrix, layers 2/3 ----------------
#define BM 128
#define LDH 40

__device__ __forceinline__ uint32_t smem_u32(const void* p) {
    return (uint32_t)__cvta_generic_to_shared(p);
}
__device__ __forceinline__ void ldsm_x4(uint32_t* r, uint32_t addr) {
    asm volatile("ldmatrix.sync.aligned.m8n8.x4.shared.b16 {%0,%1,%2,%3}, [%4];"
                 : "=r"(r[0]), "=r"(r[1]), "=r"(r[2]), "=r"(r[3]) : "r"(addr));
}
__device__ __forceinline__ void mma_f16(float* c, const uint32_t* a,
                                        uint32_t b0, uint32_t b1) {
    asm volatile(
        "mma.sync.aligned.m16n8k16.row.col.f32.f16.f16.f32 "
        "{%0,%1,%2,%3}, {%4,%5,%6,%7}, {%8,%9}, {%0,%1,%2,%3};"
        : "+f"(c[0]), "+f"(c[1]), "+f"(c[2]), "+f"(c[3])
        : "r"(a[0]), "r"(a[1]), "r"(a[2]), "r"(a[3]), "r"(b0), "r"(b1));
}

__global__ __launch_bounds__(256, 2) void layer23_tc(
    const __half* __restrict__ hinh, const __half* __restrict__ meanh,
    const __half* __restrict__ wth, const __half* __restrict__ wtl,
    const float* __restrict__ bias, float* __restrict__ out,
    __half* __restrict__ outh, int n) {
    __shared__ __half As[128 * LDH];
    __shared__ __half Bhs[128 * LDH];
    __shared__ __half Bls[128 * LDH];
    __shared__ float ss_part[2 * BM];

    int t = threadIdx.x;
    int row0 = blockIdx.x * BM;
    int wid = t >> 5, lane = t & 31;
    int warp_m = wid & 3;
    int warp_n = wid >> 2;
    int g = lane >> 2, tig = lane & 3;

    int m_st = t >> 1, part = t & 1;
    int gi_st = row0 + m_st;
    int ic_st = gi_st < n ? gi_st : n - 1;

    uint32_t a_base = smem_u32(As) +
        ((warp_m * 32 + (lane & 15)) * LDH + (lane >> 4) * 8) * 2;
    uint32_t bh_base = smem_u32(Bhs) +
        ((warp_n * 64 + (lane & 15)) * LDH + (lane >> 4) * 8) * 2;
    uint32_t bl_base = smem_u32(Bls) +
        ((warp_n * 64 + (lane & 15)) * LDH + (lane >> 4) * 8) * 2;
    const uint32_t R16 = 16 * LDH * 2;

    float acc[2][8][4];
#pragma unroll
    for (int i = 0; i < 2; i++)
#pragma unroll
        for (int j = 0; j < 8; j++)
#pragma unroll
            for (int c = 0; c < 4; c++) acc[i][j][c] = 0.f;

    for (int c = 0; c < 8; c++) {
        const __half* abase = (c < 4) ? meanh : hinh;
        int koff = (c & 3) * 32;
        {
            const uint4* asrc = (const uint4*)(abase + (size_t)ic_st * HID + koff + part * 16);
            uint4 a0 = asrc[0], a1 = asrc[1];
            __half* ad = As + m_st * LDH + part * 16;
            *(uint4*)ad = a0;
            *(uint4*)(ad + 8) = a1;

            const uint4* bhsrc = (const uint4*)(wth + m_st * 256 + c * 32 + part * 16);
            const uint4* blsrc = (const uint4*)(wtl + m_st * 256 + c * 32 + part * 16);
            uint4 bh0 = bhsrc[0], bh1 = bhsrc[1];
            uint4 bl0 = blsrc[0], bl1 = blsrc[1];
            __half* bhd = Bhs + m_st * LDH + part * 16;
            *(uint4*)bhd = bh0;
            *(uint4*)(bhd + 8) = bh1;
            __half* bld = Bls + m_st * LDH + part * 16;
            *(uint4*)bld = bl0;
            *(uint4*)(bld + 8) = bl1;
        }
        __syncthreads();

#pragma unroll
        for (int s = 0; s < 2; s++) {
            uint32_t a[2][4];
            ldsm_x4(a[0], a_base + s * 32);
            ldsm_x4(a[1], a_base + s * 32 + R16);
#pragma unroll
            for (int p = 0; p < 4; p++) {
                uint32_t bh[4], bl[4];
                ldsm_x4(bh, bh_base + p * R16 + s * 32);
                ldsm_x4(bl, bl_base + p * R16 + s * 32);
#pragma unroll
                for (int mi = 0; mi < 2; mi++) {
                    mma_f16(acc[mi][2 * p],     a[mi], bh[0], bh[2]);
                    mma_f16(acc[mi][2 * p],     a[mi], bl[0], bl[2]);
                    mma_f16(acc[mi][2 * p + 1], a[mi], bh[1], bh[3]);
                    mma_f16(acc[mi][2 * p + 1], a[mi], bl[1], bl[3]);
                }
            }
        }
        __syncthreads();
    }

    float2 bv[8];
#pragma unroll
    for (int nt = 0; nt < 8; nt++)
        bv[nt] = *(const float2*)(bias + warp_n * 64 + nt * 8 + 2 * tig);

#pragma unroll
    for (int mi = 0; mi < 2; mi++) {
#pragma unroll
        for (int h = 0; h < 2; h++) {
            float ss = 0.f;
#pragma unroll
            for (int nt = 0; nt < 8; nt++) {
                acc[mi][nt][2 * h]     += bv[nt].x;
                acc[mi][nt][2 * h + 1] += bv[nt].y;
                ss += acc[mi][nt][2 * h] * acc[mi][nt][2 * h]
                    + acc[mi][nt][2 * h + 1] * acc[mi][nt][2 * h + 1];
            }
            ss += __shfl_xor_sync(0xffffffffu, ss, 1);
            ss += __shfl_xor_sync(0xffffffffu, ss, 2);
            if (tig == 0)
                ss_part[warp_n * BM + warp_m * 32 + mi * 16 + h * 8 + g] = ss;
        }
    }
    __syncthreads();

#pragma unroll
    for (int mi = 0; mi < 2; mi++) {
#pragma unroll
        for (int h = 0; h < 2; h++) {
            int rloc = warp_m * 32 + mi * 16 + h * 8 + g;
            int gi = row0 + rloc;
            if (gi >= n) continue;
            float tot = ss_part[rloc] + ss_part[BM + rloc];
            float invn = 1.f / fmaxf(sqrtf(tot), 1e-12f);
#pragma unroll
            for (int nt = 0; nt < 8; nt++) {
                float2 o;
                o.x = tanhf(acc[mi][nt][2 * h] * invn);
                o.y = tanhf(acc[mi][nt][2 * h + 1] * invn);
                size_t off = (size_t)gi * HID + warp_n * 64 + nt * 8 + 2 * tig;
                if (out) *(float2*)(out + off) = o;
                if (outh) *(__half2*)(outh + off) = __floats2half2_rn(o.x, o.y);
            }
        }
    }
}

// ---------------- launch ----------------
extern "C" void kernel_launch(void* const* d_in, const int* in_sizes, int n_in,
                              void* d_out, int out_size) {
    const float* x       = (const float*)d_in[0];
    const int*   ei_conn = (const int*)d_in[1];
    const int*   ei_dest = (const int*)d_in[2];
    const float* w_l1 = (const float*)d_in[3];
    const float* w_r1 = (const float*)d_in[4];
    const float* b1   = (const float*)d_in[5];
    const float* w_l2 = (const float*)d_in[6];
    const float* w_r2 = (const float*)d_in[7];
    const float* b2   = (const float*)d_in[8];
    const float* w_l3 = (const float*)d_in[9];
    const float* w_r3 = (const float*)d_in[10];
    const float* b3   = (const float*)d_in[11];
    float* out = (float*)d_out;

    const int n = N_NODES;
    const int E = in_sizes[1] / 2;

    __half *p_h1h, *p_h2h, *p_aggh, *p_w2h, *p_w2l, *p_w3h, *p_w3l;
    float* p_agg8;
    int* p_cnt8;
    int *p_cnt_c, *p_cnt_d, *p_rp_c, *p_rp_d, *p_cur_c, *p_cur_d, *p_src_c, *p_src_d;
    int *p_bs_c, *p_bs_d, *p_bo_c, *p_bo_d;
    cudaGetSymbolAddress((void**)&p_h1h, g_h1h);
    cudaGetSymbolAddress((void**)&p_h2h, g_h2h);
    cudaGetSymbolAddress((void**)&p_aggh, g_aggh);
    cudaGetSymbolAddress((void**)&p_agg8, g_agg8);
    cudaGetSymbolAddress((void**)&p_cnt8, g_cnt8);
    cudaGetSymbolAddress((void**)&p_w2h, g_wt2h);
    cudaGetSymbolAddress((void**)&p_w2l, g_wt2l);
    cudaGetSymbolAddress((void**)&p_w3h, g_wt3h);
    cudaGetSymbolAddress((void**)&p_w3l, g_wt3l);
    cudaGetSymbolAddress((void**)&p_cnt_c, g_cnt_c);
    cudaGetSymbolAddress((void**)&p_cnt_d, g_cnt_d);
    cudaGetSymbolAddress((void**)&p_rp_c, g_rp_c);
    cudaGetSymbolAddress((void**)&p_rp_d, g_rp_d);
    cudaGetSymbolAddress((void**)&p_cur_c, g_cur_c);
    cudaGetSymbolAddress((void**)&p_cur_d, g_cur_d);
    cudaGetSymbolAddress((void**)&p_src_c, g_src_c);
    cudaGetSymbolAddress((void**)&p_src_d, g_src_d);
    cudaGetSymbolAddress((void**)&p_bs_c, g_bsum_c);
    cudaGetSymbolAddress((void**)&p_bs_d, g_bsum_d);
    cudaGetSymbolAddress((void**)&p_bo_c, g_boff_c);
    cudaGetSymbolAddress((void**)&p_bo_d, g_boff_d);

    static cudaStream_t sB = nullptr, sC = nullptr;
    static cudaEvent_t evFork = nullptr, evJoinD = nullptr, evJoinC = nullptr;
    if (!sB) {
        cudaStreamCreateWithFlags(&sB, cudaStreamNonBlocking);
        cudaStreamCreateWithFlags(&sC, cudaStreamNonBlocking);
        cudaEventCreateWithFlags(&evFork, cudaEventDisableTiming);
        cudaEventCreateWithFlags(&evJoinD, cudaEventDisableTiming);
        cudaEventCreateWithFlags(&evJoinC, cudaEventDisableTiming);
    }

    cudaEventRecord(evFork, 0);

    // ---- side stream B: weight prep + dest-list CSR ----
    cudaStreamWaitEvent(sB, evFork, 0);
    wprep<<<(2 * 128 * 256 + 255) / 256, 256, 0, sB>>>(w_l2, w_r2, w_l3, w_r3,
                                                       p_w2h, p_w2l, p_w3h, p_w3l);
    zero1<<<(n + 255) / 256, 256, 0, sB>>>(p_cnt_d, n);
    hist1<<<512, 256, 0, sB>>>(ei_dest, E, p_cnt_d);
    scan_p1<<<SNB, 256, 0, sB>>>(p_cnt_d, p_bs_d, n);
    scan_p2<<<1, 256, 0, sB>>>(p_bs_d, p_bo_d, p_rp_d, SNB, n);
    scan_p3<<<SNB, 256, 0, sB>>>(p_cnt_d, p_bo_d, p_rp_d, p_cur_d, n);
    fill1<<<512, 256, 0, sB>>>(ei_dest, E, p_cur_d, p_src_d);
    cudaEventRecord(evJoinD, sB);

    // ---- side stream C: conn-list CSR (needed only at layer 3) ----
    cudaStreamWaitEvent(sC, evFork, 0);
    zero1<<<(n + 255) / 256, 256, 0, sC>>>(p_cnt_c, n);
    hist1<<<512, 256, 0, sC>>>(ei_conn, E, p_cnt_c);
    scan_p1<<<SNB, 256, 0, sC>>>(p_cnt_c, p_bs_c, n);
    scan_p2<<<1, 256, 0, sC>>>(p_bs_c, p_bo_c, p_rp_c, SNB, n);
    scan_p3<<<SNB, 256, 0, sC>>>(p_cnt_c, p_bo_c, p_rp_c, p_cur_c, n);
    fill1<<<512, 256, 0, sC>>>(ei_conn, E, p_cur_c, p_src_c);
    cudaEventRecord(evJoinC, sC);

    // ---- main stream: layer 1 via CSR-free scatter aggregation ----
    zero_l1<<<1024, 256>>>(p_agg8, (size_t)n * IN_DIM, p_cnt8, n);
    scatter8<<<(E + 255) / 256, 256>>>(x, ei_conn, E, p_agg8, p_cnt8);
    layer1_direct<<<(n + 7) / 8, 256>>>(x, p_agg8, p_cnt8, w_l1, w_r1, b1, p_h1h, n);

    // ---- layer 2 (dest) ----
    cudaStreamWaitEvent(0, evJoinD, 0);
    gather128h<<<(n * 32 + 255) / 256, 256>>>(p_h1h, p_rp_d, p_src_d, p_aggh, n);
    layer23_tc<<<(n + BM - 1) / BM, 256>>>(p_h1h, p_aggh, p_w2h, p_w2l, b2,
                                           nullptr, p_h2h, n);

    // ---- layer 3 (conn) ----
    cudaStreamWaitEvent(0, evJoinC, 0);
    gather128h<<<(n * 32 + 255) / 256, 256>>>(p_h2h, p_rp_c, p_src_c, p_aggh, n);
    layer23_tc<<<(n + BM - 1) / BM, 256>>>(p_h2h, p_aggh, p_w3h, p_w3l, b3,
                                           out, nullptr, n);
}

// round 15
// speedup vs baseline: 1.3177x; 1.0634x over previous
#include <cuda_runtime.h>
#include <cuda_fp16.h>
#include <cstdint>

#define N_NODES 100000
#define N_EDGES 1600000
#define HID 128
#define IN_DIM 8
#define SCH 512
#define SNB ((N_NODES + SCH - 1) / SCH)  // 196

// ---------------- scratch (static __device__, no allocation) ----------------
__device__ __half g_h1h[(size_t)N_NODES * HID];
__device__ __half g_h2h[(size_t)N_NODES * HID];
__device__ __half g_aggh[(size_t)N_NODES * HID];
__device__ __half g_wt2h[128 * 256];
__device__ __half g_wt2l[128 * 256];
__device__ __half g_wt3h[128 * 256];
__device__ __half g_wt3l[128 * 256];
__device__ int g_cnt_c[N_NODES];
__device__ int g_cnt_d[N_NODES];
__device__ int g_rp_c[N_NODES + 1];
__device__ int g_rp_d[N_NODES + 1];
__device__ int g_cur_c[N_NODES];
__device__ int g_cur_d[N_NODES];
__device__ int g_src_c[N_EDGES];
__device__ int g_src_d[N_EDGES];
__device__ int g_bsum_c[SNB];
__device__ int g_bsum_d[SNB];
__device__ int g_boff_c[SNB];
__device__ int g_boff_d[SNB];

// ---------------- CSR build (per-list) ----------------
__global__ void zero1(int* a, int n) {
    int i = blockIdx.x * blockDim.x + threadIdx.x;
    int st = gridDim.x * blockDim.x;
    for (; i < n; i += st) a[i] = 0;
}
__global__ void hist1(const int* __restrict__ ei, int E, int* cnt) {
    int i = blockIdx.x * blockDim.x + threadIdx.x;
    int st = gridDim.x * blockDim.x;
    for (; i < E; i += st) atomicAdd(&cnt[ei[E + i]], 1);
}

__global__ __launch_bounds__(256) void scan_p1(const int* __restrict__ cnt,
                                               int* __restrict__ bsum, int n) {
    __shared__ int s[8];
    int b = blockIdx.x, t = threadIdx.x;
    int i0 = b * SCH + t;
    int v = 0;
    if (i0 < n) v += cnt[i0];
    if (i0 + 256 < n) v += cnt[i0 + 256];
#pragma unroll
    for (int o = 16; o >= 1; o >>= 1) v += __shfl_xor_sync(0xffffffffu, v, o);
    if ((t & 31) == 0) s[t >> 5] = v;
    __syncthreads();
    if (t < 8) {
        int w = s[t];
#pragma unroll
        for (int o = 4; o >= 1; o >>= 1) w += __shfl_xor_sync(0xffu, w, o);
        if (t == 0) bsum[b] = w;
    }
}

__global__ __launch_bounds__(256) void scan_p2(const int* __restrict__ bsum,
                                               int* __restrict__ boff,
                                               int* __restrict__ rp, int nb, int n) {
    __shared__ int s[256];
    int t = threadIdx.x;
    int v = (t < nb) ? bsum[t] : 0;
    s[t] = v;
    __syncthreads();
#pragma unroll
    for (int o = 1; o < 256; o <<= 1) {
        int u = (t >= o) ? s[t - o] : 0;
        __syncthreads();
        s[t] += u;
        __syncthreads();
    }
    if (t < nb) boff[t] = s[t] - v;
    if (t == 255) rp[n] = s[255];
}

__global__ __launch_bounds__(256) void scan_p3(const int* __restrict__ cnt,
                                               const int* __restrict__ boff,
                                               int* __restrict__ rp,
                                               int* __restrict__ cur, int n) {
    __shared__ int wsum[8];
    int b = blockIdx.x, t = threadIdx.x;
    int lane = t & 31, wrp = t >> 5;
    int i0 = b * SCH + 2 * t;
    int c0 = (i0 < n) ? cnt[i0] : 0;
    int c1 = (i0 + 1 < n) ? cnt[i0 + 1] : 0;
    int ps = c0 + c1;
    int x = ps;
#pragma unroll
    for (int o = 1; o < 32; o <<= 1) {
        int u = __shfl_up_sync(0xffffffffu, x, o);
        if (lane >= o) x += u;
    }
    if (lane == 31) wsum[wrp] = x;
    __syncthreads();
    if (t < 8) {
        int w = wsum[t];
        int y = w;
#pragma unroll
        for (int o = 1; o < 8; o <<= 1) {
            int u = __shfl_up_sync(0xffu, y, o);
            if (t >= o) y += u;
        }
        wsum[t] = y - w;
    }
    __syncthreads();
    int woff = wsum[wrp];
    int pre = boff[b] + woff + (x - ps);
    if (i0 < n) { rp[i0] = pre; cur[i0] = pre; }
    if (i0 + 1 < n) { rp[i0 + 1] = pre + c0; cur[i0 + 1] = pre + c0; }
}

__global__ void fill1(const int* __restrict__ ei, int E, int* cur,
                      int* __restrict__ srcl) {
    int i = blockIdx.x * blockDim.x + threadIdx.x;
    int st = gridDim.x * blockDim.x;
    for (; i < E; i += st) {
        int s = ei[i], d = ei[E + i];
        srcl[atomicAdd(&cur[d], 1)] = s;
    }
}

// ---------------- weight prep: W[k][n] fp32 -> Wt[n][256] fp16 hi/lo ----------------
__global__ void wprep(const float* __restrict__ wl2, const float* __restrict__ wr2,
                      const float* __restrict__ wl3, const float* __restrict__ wr3,
                      __half* w2h, __half* w2l, __half* w3h, __half* w3l) {
    int i = blockIdx.x * blockDim.x + threadIdx.x;
    if (i >= 2 * 128 * 256) return;
    int layer = i >> 15;
    int rem = i & 32767;
    int nrow = rem >> 8, k = rem & 255;
    const float* wlm = layer ? wl3 : wl2;
    const float* wrm = layer ? wr3 : wr2;
    float v = (k < 128) ? wlm[k * 128 + nrow] : wrm[(k - 128) * 128 + nrow];
    __half h = __float2half(v);
    __half l = __float2half(v - __half2float(h));
    (layer ? w3h : w2h)[nrow * 256 + k] = h;
    (layer ? w3l : w2l)[nrow * 256 + k] = l;
}

// ---------------- gather-mean over fp16 rows -> fp16 mean, d=128 ----------------
// one warp per node; 16 lanes per 256B row; 4-row unrolled main loop per half-warp
__device__ __forceinline__ void acc_row(float* acc, const uint4& r) {
#pragma unroll
    for (int q = 0; q < 4; q++) {
        float2 f = __half22float2(*(const __half2*)(&r.x + q));
        acc[2 * q]     += f.x;
        acc[2 * q + 1] += f.y;
    }
}

__global__ void gather128h(const __half* __restrict__ h, const int* __restrict__ rp,
                           const int* __restrict__ src, __half* __restrict__ outh, int n) {
    int node = (blockIdx.x * blockDim.x + threadIdx.x) >> 5;
    int lane = threadIdx.x & 31;
    if (node >= n) return;
    int half = lane >> 4, li = lane & 15;
    int b = __ldg(rp + node), e = __ldg(rp + node + 1);
    float acc[8];
#pragma unroll
    for (int k = 0; k < 8; k++) acc[k] = 0.f;

    int j = b + half;
    // 4 rows in flight per half-warp (8 per warp)
    for (; j + 6 < e; j += 8) {
        int s0 = __ldg(src + j);
        int s1 = __ldg(src + j + 2);
        int s2 = __ldg(src + j + 4);
        int s3 = __ldg(src + j + 6);
        uint4 r0 = *(const uint4*)(h + (size_t)s0 * HID + li * 8);
        uint4 r1 = *(const uint4*)(h + (size_t)s1 * HID + li * 8);
        uint4 r2 = *(const uint4*)(h + (size_t)s2 * HID + li * 8);
        uint4 r3 = *(const uint4*)(h + (size_t)s3 * HID + li * 8);
        acc_row(acc, r0);
        acc_row(acc, r1);
        acc_row(acc, r2);
        acc_row(acc, r3);
    }
    for (; j + 2 < e; j += 4) {
        int s0 = __ldg(src + j);
        int s1 = __ldg(src + j + 2);
        uint4 r0 = *(const uint4*)(h + (size_t)s0 * HID + li * 8);
        uint4 r1 = *(const uint4*)(h + (size_t)s1 * HID + li * 8);
        acc_row(acc, r0);
        acc_row(acc, r1);
    }
    if (j < e) {
        int s0 = __ldg(src + j);
        uint4 r0 = *(const uint4*)(h + (size_t)s0 * HID + li * 8);
        acc_row(acc, r0);
    }
#pragma unroll
    for (int k = 0; k < 8; k++)
        acc[k] += __shfl_xor_sync(0xffffffffu, acc[k], 16);

    if (half == 0) {
        float inv = 1.f / fmaxf((float)(e - b), 1.f);
        uint4 o;
        ((__half2*)&o)[0] = __floats2half2_rn(acc[0] * inv, acc[1] * inv);
        ((__half2*)&o)[1] = __floats2half2_rn(acc[2] * inv, acc[3] * inv);
        ((__half2*)&o)[2] = __floats2half2_rn(acc[4] * inv, acc[5] * inv);
        ((__half2*)&o)[3] = __floats2half2_rn(acc[6] * inv, acc[7] * inv);
        *(uint4*)(outh + (size_t)node * HID + li * 8) = o;
    }
}

// ---------------- layer 1 fused: gather-mean(d=8) + GEMM + norm + tanh ----------------
__global__ void layer1_fused(const float* __restrict__ x,
                             const int* __restrict__ rp, const int* __restrict__ src,
                             const float* __restrict__ wl, const float* __restrict__ wr,
                             const float* __restrict__ bias,
                             __half* __restrict__ outh, int n) {
    __shared__ float s_wl[IN_DIM * HID];
    __shared__ float s_wr[IN_DIM * HID];
    __shared__ float s_b[HID];
    for (int i = threadIdx.x; i < IN_DIM * HID; i += blockDim.x) {
        s_wl[i] = wl[i];
        s_wr[i] = wr[i];
    }
    if (threadIdx.x < HID) s_b[threadIdx.x] = bias[threadIdx.x];
    __syncthreads();

    int warp = threadIdx.x >> 5, lane = threadIdx.x & 31;
    int node = blockIdx.x * (blockDim.x >> 5) + warp;
    if (node >= n) return;
    int grp = lane >> 3, dim = lane & 7;

    int b = __ldg(rp + node), e = __ldg(rp + node + 1);
    float acc8 = 0.f;
    for (int j = b + grp; j < e; j += 4) {
        int s0 = __ldg(src + j);
        acc8 += __ldg(x + (size_t)s0 * IN_DIM + dim);
    }
    acc8 += __shfl_xor_sync(0xffffffffu, acc8, 8);
    acc8 += __shfl_xor_sync(0xffffffffu, acc8, 16);
    acc8 *= 1.f / fmaxf((float)(e - b), 1.f);

    float my_x = __ldg(x + (size_t)node * IN_DIM + dim);

    float xs[8], as[8];
#pragma unroll
    for (int k = 0; k < 8; k++) {
        xs[k] = __shfl_sync(0xffffffffu, my_x, k);
        as[k] = __shfl_sync(0xffffffffu, acc8, k);
    }
    float acc[4];
#pragma unroll
    for (int c = 0; c < 4; c++) {
        int j = lane + 32 * c;
        float a = s_b[j];
#pragma unroll
        for (int k = 0; k < 8; k++)
            a += as[k] * s_wl[k * HID + j] + xs[k] * s_wr[k * HID + j];
        acc[c] = a;
    }
    float ss = acc[0] * acc[0] + acc[1] * acc[1] + acc[2] * acc[2] + acc[3] * acc[3];
#pragma unroll
    for (int o = 16; o >= 1; o >>= 1) ss += __shfl_xor_sync(0xffffffffu, ss, o);
    float invn = 1.f / fmaxf(sqrtf(ss), 1e-12f);
#pragma unroll
    for (int c = 0; c < 4; c++) {
        float v = tanhf(acc[c] * invn);
        outh[(size_t)node * HID + lane + 32 * c] = __float2half(v);
    }
}

// ---------------- fp16 tensor-core GEMM with ldmatrix, layers 2/3 ----------------
#define BM 128
#define LDH 40

__device__ __forceinline__ uint32_t smem_u32(const void* p) {
    return (uint32_t)__cvta_generic_to_shared(p);
}
__device__ __forceinline__ void ldsm_x4(uint32_t* r, uint32_t addr) {
    asm volatile("ldmatrix.sync.aligned.m8n8.x4.shared.b16 {%0,%1,%2,%3}, [%4];"
                 : "=r"(r[0]), "=r"(r[1]), "=r"(r[2]), "=r"(r[3]) : "r"(addr));
}
__device__ __forceinline__ void mma_f16(float* c, const uint32_t* a,
                                        uint32_t b0, uint32_t b1) {
    asm volatile(
        "mma.sync.aligned.m16n8k16.row.col.f32.f16.f16.f32 "
        "{%0,%1,%2,%3}, {%4,%5,%6,%7}, {%8,%9}, {%0,%1,%2,%3};"
        : "+f"(c[0]), "+f"(c[1]), "+f"(c[2]), "+f"(c[3])
        : "r"(a[0]), "r"(a[1]), "r"(a[2]), "r"(a[3]), "r"(b0), "r"(b1));
}

__global__ __launch_bounds__(256, 2) void layer23_tc(
    const __half* __restrict__ hinh, const __half* __restrict__ meanh,
    const __half* __restrict__ wth, const __half* __restrict__ wtl,
    const float* __restrict__ bias, float* __restrict__ out,
    __half* __restrict__ outh, int n) {
    __shared__ __half As[128 * LDH];
    __shared__ __half Bhs[128 * LDH];
    __shared__ __half Bls[128 * LDH];
    __shared__ float ss_part[2 * BM];

    int t = threadIdx.x;
    int row0 = blockIdx.x * BM;
    int wid = t >> 5, lane = t & 31;
    int warp_m = wid & 3;
    int warp_n = wid >> 2;
    int g = lane >> 2, tig = lane & 3;

    int m_st = t >> 1, part = t & 1;
    int gi_st = row0 + m_st;
    int ic_st = gi_st < n ? gi_st : n - 1;

    uint32_t a_base = smem_u32(As) +
        ((warp_m * 32 + (lane & 15)) * LDH + (lane >> 4) * 8) * 2;
    uint32_t bh_base = smem_u32(Bhs) +
        ((warp_n * 64 + (lane & 15)) * LDH + (lane >> 4) * 8) * 2;
    uint32_t bl_base = smem_u32(Bls) +
        ((warp_n * 64 + (lane & 15)) * LDH + (lane >> 4) * 8) * 2;
    const uint32_t R16 = 16 * LDH * 2;

    float acc[2][8][4];
#pragma unroll
    for (int i = 0; i < 2; i++)
#pragma unroll
        for (int j = 0; j < 8; j++)
#pragma unroll
            for (int c = 0; c < 4; c++) acc[i][j][c] = 0.f;

    for (int c = 0; c < 8; c++) {
        const __half* abase = (c < 4) ? meanh : hinh;
        int koff = (c & 3) * 32;
        {
            const uint4* asrc = (const uint4*)(abase + (size_t)ic_st * HID + koff + part * 16);
            uint4 a0 = asrc[0], a1 = asrc[1];
            __half* ad = As + m_st * LDH + part * 16;
            *(uint4*)ad = a0;
            *(uint4*)(ad + 8) = a1;

            const uint4* bhsrc = (const uint4*)(wth + m_st * 256 + c * 32 + part * 16);
            const uint4* blsrc = (const uint4*)(wtl + m_st * 256 + c * 32 + part * 16);
            uint4 bh0 = bhsrc[0], bh1 = bhsrc[1];
            uint4 bl0 = blsrc[0], bl1 = blsrc[1];
            __half* bhd = Bhs + m_st * LDH + part * 16;
            *(uint4*)bhd = bh0;
            *(uint4*)(bhd + 8) = bh1;
            __half* bld = Bls + m_st * LDH + part * 16;
            *(uint4*)bld = bl0;
            *(uint4*)(bld + 8) = bl1;
        }
        __syncthreads();

#pragma unroll
        for (int s = 0; s < 2; s++) {
            uint32_t a[2][4];
            ldsm_x4(a[0], a_base + s * 32);
            ldsm_x4(a[1], a_base + s * 32 + R16);
#pragma unroll
            for (int p = 0; p < 4; p++) {
                uint32_t bh[4], bl[4];
                ldsm_x4(bh, bh_base + p * R16 + s * 32);
                ldsm_x4(bl, bl_base + p * R16 + s * 32);
#pragma unroll
                for (int mi = 0; mi < 2; mi++) {
                    mma_f16(acc[mi][2 * p],     a[mi], bh[0], bh[2]);
                    mma_f16(acc[mi][2 * p],     a[mi], bl[0], bl[2]);
                    mma_f16(acc[mi][2 * p + 1], a[mi], bh[1], bh[3]);
                    mma_f16(acc[mi][2 * p + 1], a[mi], bl[1], bl[3]);
                }
            }
        }
        __syncthreads();
    }

    float2 bv[8];
#pragma unroll
    for (int nt = 0; nt < 8; nt++)
        bv[nt] = *(const float2*)(bias + warp_n * 64 + nt * 8 + 2 * tig);

#pragma unroll
    for (int mi = 0; mi < 2; mi++) {
#pragma unroll
        for (int h = 0; h < 2; h++) {
            float ss = 0.f;
#pragma unroll
            for (int nt = 0; nt < 8; nt++) {
                acc[mi][nt][2 * h]     += bv[nt].x;
                acc[mi][nt][2 * h + 1] += bv[nt].y;
                ss += acc[mi][nt][2 * h] * acc[mi][nt][2 * h]
                    + acc[mi][nt][2 * h + 1] * acc[mi][nt][2 * h + 1];
            }
            ss += __shfl_xor_sync(0xffffffffu, ss, 1);
            ss += __shfl_xor_sync(0xffffffffu, ss, 2);
            if (tig == 0)
                ss_part[warp_n * BM + warp_m * 32 + mi * 16 + h * 8 + g] = ss;
        }
    }
    __syncthreads();

#pragma unroll
    for (int mi = 0; mi < 2; mi++) {
#pragma unroll
        for (int h = 0; h < 2; h++) {
            int rloc = warp_m * 32 + mi * 16 + h * 8 + g;
            int gi = row0 + rloc;
            if (gi >= n) continue;
            float tot = ss_part[rloc] + ss_part[BM + rloc];
            float invn = 1.f / fmaxf(sqrtf(tot), 1e-12f);
#pragma unroll
            for (int nt = 0; nt < 8; nt++) {
                float2 o;
                o.x = tanhf(acc[mi][nt][2 * h] * invn);
                o.y = tanhf(acc[mi][nt][2 * h + 1] * invn);
                size_t off = (size_t)gi * HID + warp_n * 64 + nt * 8 + 2 * tig;
                if (out) *(float2*)(out + off) = o;
                if (outh) *(__half2*)(outh + off) = __floats2half2_rn(o.x, o.y);
            }
        }
    }
}

// ---------------- launch ----------------
extern "C" void kernel_launch(void* const* d_in, const int* in_sizes, int n_in,
                              void* d_out, int out_size) {
    const float* x       = (const float*)d_in[0];
    const int*   ei_conn = (const int*)d_in[1];
    const int*   ei_dest = (const int*)d_in[2];
    const float* w_l1 = (const float*)d_in[3];
    const float* w_r1 = (const float*)d_in[4];
    const float* b1   = (const float*)d_in[5];
    const float* w_l2 = (const float*)d_in[6];
    const float* w_r2 = (const float*)d_in[7];
    const float* b2   = (const float*)d_in[8];
    const float* w_l3 = (const float*)d_in[9];
    const float* w_r3 = (const float*)d_in[10];
    const float* b3   = (const float*)d_in[11];
    float* out = (float*)d_out;

    const int n = N_NODES;
    const int E = in_sizes[1] / 2;

    __half *p_h1h, *p_h2h, *p_aggh, *p_w2h, *p_w2l, *p_w3h, *p_w3l;
    int *p_cnt_c, *p_cnt_d, *p_rp_c, *p_rp_d, *p_cur_c, *p_cur_d, *p_src_c, *p_src_d;
    int *p_bs_c, *p_bs_d, *p_bo_c, *p_bo_d;
    cudaGetSymbolAddress((void**)&p_h1h, g_h1h);
    cudaGetSymbolAddress((void**)&p_h2h, g_h2h);
    cudaGetSymbolAddress((void**)&p_aggh, g_aggh);
    cudaGetSymbolAddress((void**)&p_w2h, g_wt2h);
    cudaGetSymbolAddress((void**)&p_w2l, g_wt2l);
    cudaGetSymbolAddress((void**)&p_w3h, g_wt3h);
    cudaGetSymbolAddress((void**)&p_w3l, g_wt3l);
    cudaGetSymbolAddress((void**)&p_cnt_c, g_cnt_c);
    cudaGetSymbolAddress((void**)&p_cnt_d, g_cnt_d);
    cudaGetSymbolAddress((void**)&p_rp_c, g_rp_c);
    cudaGetSymbolAddress((void**)&p_rp_d, g_rp_d);
    cudaGetSymbolAddress((void**)&p_cur_c, g_cur_c);
    cudaGetSymbolAddress((void**)&p_cur_d, g_cur_d);
    cudaGetSymbolAddress((void**)&p_src_c, g_src_c);
    cudaGetSymbolAddress((void**)&p_src_d, g_src_d);
    cudaGetSymbolAddress((void**)&p_bs_c, g_bsum_c);
    cudaGetSymbolAddress((void**)&p_bs_d, g_bsum_d);
    cudaGetSymbolAddress((void**)&p_bo_c, g_boff_c);
    cudaGetSymbolAddress((void**)&p_bo_d, g_boff_d);

    static cudaStream_t sB = nullptr;
    static cudaEvent_t evFork = nullptr, evJoin = nullptr;
    if (!sB) {
        cudaStreamCreateWithFlags(&sB, cudaStreamNonBlocking);
        cudaEventCreateWithFlags(&evFork, cudaEventDisableTiming);
        cudaEventCreateWithFlags(&evJoin, cudaEventDisableTiming);
    }

    // ---- fork: weight prep + dest-list CSR on side stream ----
    cudaEventRecord(evFork, 0);
    cudaStreamWaitEvent(sB, evFork, 0);
    wprep<<<(2 * 128 * 256 + 255) / 256, 256, 0, sB>>>(w_l2, w_r2, w_l3, w_r3,
                                                       p_w2h, p_w2l, p_w3h, p_w3l);
    zero1<<<(n + 255) / 256, 256, 0, sB>>>(p_cnt_d, n);
    hist1<<<1024, 256, 0, sB>>>(ei_dest, E, p_cnt_d);
    scan_p1<<<SNB, 256, 0, sB>>>(p_cnt_d, p_bs_d, n);
    scan_p2<<<1, 256, 0, sB>>>(p_bs_d, p_bo_d, p_rp_d, SNB, n);
    scan_p3<<<SNB, 256, 0, sB>>>(p_cnt_d, p_bo_d, p_rp_d, p_cur_d, n);
    fill1<<<1024, 256, 0, sB>>>(ei_dest, E, p_cur_d, p_src_d);
    cudaEventRecord(evJoin, sB);

    // ---- main stream: conn-list CSR + layer 1 ----
    zero1<<<(n + 255) / 256, 256>>>(p_cnt_c, n);
    hist1<<<1024, 256>>>(ei_conn, E, p_cnt_c);
    scan_p1<<<SNB, 256>>>(p_cnt_c, p_bs_c, n);
    scan_p2<<<1, 256>>>(p_bs_c, p_bo_c, p_rp_c, SNB, n);
    scan_p3<<<SNB, 256>>>(p_cnt_c, p_bo_c, p_rp_c, p_cur_c, n);
    fill1<<<1024, 256>>>(ei_conn, E, p_cur_c, p_src_c);
    layer1_fused<<<(n + 7) / 8, 256>>>(x, p_rp_c, p_src_c, w_l1, w_r1, b1, p_h1h, n);

    // ---- join, then layer 2 (dest) ----
    cudaStreamWaitEvent(0, evJoin, 0);
    gather128h<<<(n * 32 + 255) / 256, 256>>>(p_h1h, p_rp_d, p_src_d, p_aggh, n);
    layer23_tc<<<(n + BM - 1) / BM, 256>>>(p_h1h, p_aggh, p_w2h, p_w2l, b2,
                                           nullptr, p_h2h, n);

    // ---- layer 3 (conn) ----
    gather128h<<<(n * 32 + 255) / 256, 256>>>(p_h2h, p_rp_c, p_src_c, p_aggh, n);
    layer23_tc<<<(n + BM - 1) / BM, 256>>>(p_h2h, p_aggh, p_w3h, p_w3l, b3,
                                           out, nullptr, n);
}